// round 14
// baseline (speedup 1.0000x reference)
#include <cuda_runtime.h>
#include <cuda_fp16.h>
#include <cstdint>
#include <math.h>

#define BB   64
#define NN   4096
#define DD   64
#define HH   256
#define SS   1024
#define TOT  49152   // 3 * D * H
#define WPB  24576   // half2 words per batch (3*D*H/2)

// raw hypernet output (k1 -> k2)
__device__ float g_params[BB * (size_t)TOT];
// normalized fp16 weights, half2-packed along k, XOR-swizzled (k2 -> k3)
__device__ uint32_t g_wT[BB * (size_t)WPB];

// ======================= helpers =======================
__device__ __forceinline__ float tanha(float x) {
    float y;
    asm("tanh.approx.f32 %0, %1;" : "=f"(y) : "f"(x));
    return y;
}
__device__ __forceinline__ uint32_t pack2(float lo, float hi) {
    __half2 h = __floats2half2_rn(lo, hi);
    return *(uint32_t*)&h;
}
__device__ __forceinline__ uint32_t smem_u32(const void* p) {
    uint32_t a;
    asm("{ .reg .u64 t; cvta.to.shared.u64 t, %1; cvt.u32.u64 %0, t; }" : "=r"(a) : "l"(p));
    return a;
}
__device__ __forceinline__ void cpa16(uint32_t dst, const void* src) {
    asm volatile("cp.async.cg.shared.global [%0], [%1], 16;" :: "r"(dst), "l"(src));
}
#define CP_COMMIT() asm volatile("cp.async.commit_group;" ::: "memory")
#define CP_WAIT0()  asm volatile("cp.async.wait_group 0;" ::: "memory")
#define CP_WAIT1()  asm volatile("cp.async.wait_group 1;" ::: "memory")

// D += A * B  (m16n8k16, fp16 inputs, fp32 accum)
__device__ __forceinline__ void mma_f16(float* d, const uint32_t* a, uint32_t b0, uint32_t b1) {
    asm volatile("mma.sync.aligned.m16n8k16.row.col.f32.f16.f16.f32 "
                 "{%0,%1,%2,%3}, {%4,%5,%6,%7}, {%8,%9}, {%0,%1,%2,%3};"
                 : "+f"(d[0]), "+f"(d[1]), "+f"(d[2]), "+f"(d[3])
                 : "r"(a[0]), "r"(a[1]), "r"(a[2]), "r"(a[3]), "r"(b0), "r"(b1));
}

// ======================= kernel 1: fp16 mma GEMM, cooperative smem pack =======================
// staging fp32: A [2][64][36], B [2][32][136]; packed fp16: pA [2][64][20] w, pB [2][16][132] w
#define K1_AF 2304
#define K1_BF 4352
#define K1_PAW 1280
#define K1_PBW 2112
#define K1_SMEM ((2 * (K1_AF + K1_BF) + 2 * (K1_PAW + K1_PBW)) * 4)   // 80384 B

__global__ __launch_bounds__(256) void k1_mma(const float* __restrict__ s,
                                              const float* __restrict__ W,
                                              const float* __restrict__ bias) {
    extern __shared__ uint32_t sk1[];
    float* sAf = (float*)sk1;                       // 2*2304
    float* sBf = (float*)(sk1 + 2 * K1_AF);         // 2*4352
    uint32_t* pA = sk1 + 2 * (K1_AF + K1_BF);       // 2*1280
    uint32_t* pB = pA + 2 * K1_PAW;                 // 2*2112
    const int n0  = blockIdx.x * 128;
    const int tid = threadIdx.x;
    const int w = tid >> 5, lane = tid & 31;
    const int r = lane >> 2, q = lane & 3;
    const int m0 = (w & 1) * 32, nw = (w >> 1) * 32;
    const uint32_t sbA = smem_u32(sAf), sbB = smem_u32(sBf);

    #define K1_LOAD(st, k0) do {                                                   \
        _Pragma("unroll")                                                          \
        for (int i = 0; i < 2; i++) {                                              \
            int c = tid + i * 256;                                                 \
            int row = c >> 3, cc = c & 7;                                          \
            cpa16(sbA + (uint32_t)((st) * K1_AF + row * 36 + cc * 4) * 4,          \
                  s + (size_t)row * SS + (k0) + cc * 4);                           \
        }                                                                          \
        _Pragma("unroll")                                                          \
        for (int i = 0; i < 4; i++) {                                              \
            int c = tid + i * 256;                                                 \
            int row = c >> 5, cc = c & 31;                                         \
            cpa16(sbB + (uint32_t)((st) * K1_BF + row * 136 + cc * 4) * 4,         \
                  W + (size_t)((k0) + row) * TOT + n0 + cc * 4);                   \
        }                                                                          \
    } while (0)

    // cooperative fp32 -> fp16 pack of one stage
    #define K1_PACK(st) do {                                                       \
        const float* Af = sAf + (st) * K1_AF;                                      \
        const float* Bf = sBf + (st) * K1_BF;                                      \
        uint32_t* Ap = pA + (st) * K1_PAW;                                         \
        uint32_t* Bpk = pB + (st) * K1_PBW;                                        \
        {                                                                          \
            int row = tid >> 2, c8 = (tid & 3) * 8;                                \
            float4 u = *(const float4*)(Af + row * 36 + c8);                       \
            float4 v = *(const float4*)(Af + row * 36 + c8 + 4);                   \
            uint4 wv;                                                              \
            wv.x = pack2(u.x, u.y); wv.y = pack2(u.z, u.w);                        \
            wv.z = pack2(v.x, v.y); wv.w = pack2(v.z, v.w);                        \
            *(uint2*)(Ap + row * 20 + (c8 >> 1))     = make_uint2(wv.x, wv.y);     \
            *(uint2*)(Ap + row * 20 + (c8 >> 1) + 2) = make_uint2(wv.z, wv.w);     \
        }                                                                          \
        {                                                                          \
            int kp = tid >> 4, c8 = (tid & 15) * 8;                                \
            float4 e0 = *(const float4*)(Bf + (2 * kp) * 136 + c8);                \
            float4 e1 = *(const float4*)(Bf + (2 * kp) * 136 + c8 + 4);            \
            float4 o0 = *(const float4*)(Bf + (2 * kp + 1) * 136 + c8);            \
            float4 o1 = *(const float4*)(Bf + (2 * kp + 1) * 136 + c8 + 4);        \
            uint4 w0, w1;                                                          \
            w0.x = pack2(e0.x, o0.x); w0.y = pack2(e0.y, o0.y);                    \
            w0.z = pack2(e0.z, o0.z); w0.w = pack2(e0.w, o0.w);                    \
            w1.x = pack2(e1.x, o1.x); w1.y = pack2(e1.y, o1.y);                    \
            w1.z = pack2(e1.z, o1.z); w1.w = pack2(e1.w, o1.w);                    \
            *(uint4*)(Bpk + kp * 132 + c8)     = w0;                               \
            *(uint4*)(Bpk + kp * 132 + c8 + 4) = w1;                               \
        }                                                                          \
    } while (0)

    float acc[2][4][4];
    #pragma unroll
    for (int mf = 0; mf < 2; mf++)
        #pragma unroll
        for (int nf = 0; nf < 4; nf++)
            acc[mf][nf][0] = acc[mf][nf][1] = acc[mf][nf][2] = acc[mf][nf][3] = 0.f;

    K1_LOAD(0, 0);  CP_COMMIT();
    K1_LOAD(1, 32); CP_COMMIT();

    for (int ks = 0; ks < 32; ks++) {
        CP_WAIT1();
        __syncthreads();
        const int st = ks & 1;
        K1_PACK(st);
        __syncthreads();
        // staging st is free now: prefetch next chunk into it while mma runs on packed st
        const int kn = (ks + 2) * 32;
        if (kn < SS) { K1_LOAD(st, kn); }
        CP_COMMIT();

        const uint32_t* Ap = pA + st * K1_PAW;
        const uint32_t* Bpk = pB + st * K1_PBW;
        #pragma unroll
        for (int t = 0; t < 2; t++) {
            uint32_t a[2][4];
            #pragma unroll
            for (int mf = 0; mf < 2; mf++) {
                const uint32_t* ab = Ap + (m0 + mf * 16 + r) * 20 + t * 8 + q;
                a[mf][0] = ab[0];
                a[mf][1] = ab[160];     // +8 rows
                a[mf][2] = ab[4];
                a[mf][3] = ab[164];
            }
            const uint32_t* b0r = Bpk + (t * 8 + q) * 132;
            const uint32_t* b1r = Bpk + (t * 8 + q + 4) * 132;
            #pragma unroll
            for (int nf = 0; nf < 4; nf++) {
                const int cb = nw + nf * 8 + r;
                uint32_t b0 = b0r[cb], b1 = b1r[cb];
                mma_f16(acc[0][nf], a[0], b0, b1);
                mma_f16(acc[1][nf], a[1], b0, b1);
            }
        }
    }

    #pragma unroll
    for (int nf = 0; nf < 4; nf++) {
        float2 bv = *(const float2*)(bias + n0 + nw + nf * 8 + 2 * q);
        #pragma unroll
        for (int mf = 0; mf < 2; mf++) {
            const int mr = m0 + mf * 16 + r;
            float* o0 = g_params + (size_t)mr * TOT + n0 + nw + nf * 8 + 2 * q;
            *(float2*)o0 = make_float2(acc[mf][nf][0] + bv.x, acc[mf][nf][1] + bv.y);
            float* o1 = g_params + (size_t)(mr + 8) * TOT + n0 + nw + nf * 8 + 2 * q;
            *(float2*)o1 = make_float2(acc[mf][nf][2] + bv.x, acc[mf][nf][3] + bv.y);
        }
    }
    #undef K1_LOAD
    #undef K1_PACK
}

// ======================= kernel 2: normalize -> fp16 swizzled, grid (64, 4) (frozen) =======================
__global__ __launch_bounds__(256) void k2_normalize() {
    __shared__ float red[256];
    __shared__ float sinv[64];
    const int b = blockIdx.x, quad = blockIdx.y, tid = threadIdx.x;
    const float* P = g_params + (size_t)b * TOT;
    uint32_t* dst = g_wT + (size_t)b * WPB;

    #pragma unroll
    for (int m = 0; m < 2; m++) {
        const float* src = P + m * 16384;
        const int hl = tid & 63, part = tid >> 6;
        const int h = quad * 64 + hl;
        {
            float ss = 0.f;
            #pragma unroll 4
            for (int d = part * 16; d < part * 16 + 16; d++) {
                float v = src[d * 256 + h];
                ss += v * v;
            }
            red[tid] = ss;
        }
        __syncthreads();
        if (tid < 64)
            sinv[tid] = 1.f / fmaxf(sqrtf(red[tid] + red[tid + 64] + red[tid + 128] + red[tid + 192]), 1e-12f);
        __syncthreads();
        #pragma unroll
        for (int i = 0; i < 8; i++) {
            int idx = tid + i * 256;
            int kp = idx >> 6, hl2 = idx & 63;
            int h2 = quad * 64 + hl2;
            float inv = sinv[hl2];
            float a = src[(2 * kp) * 256 + h2] * inv;
            float c = src[(2 * kp + 1) * 256 + h2] * inv;
            dst[m * 8192 + kp * 256 + (h2 ^ ((kp & 3) << 3))] = pack2(a, c);
        }
        __syncthreads();
    }
    {
        const float* src = P + 32768;
        const int dl = tid & 15, part = tid >> 4;
        const int d = quad * 16 + dl;
        {
            float ss = 0.f;
            #pragma unroll 4
            for (int h = part * 16; h < part * 16 + 16; h++) {
                float v = src[h * 64 + d];
                ss += v * v;
            }
            red[tid] = ss;
        }
        __syncthreads();
        if (tid < 16) {
            float t = 0.f;
            #pragma unroll
            for (int p = 0; p < 16; p++) t += red[p * 16 + tid];
            sinv[tid] = 1.f / fmaxf(sqrtf(t), 1e-12f);
        }
        __syncthreads();
        #pragma unroll
        for (int i = 0; i < 8; i++) {
            int idx = tid + i * 256;
            int hp = idx >> 4, dl2 = idx & 15;
            int d2 = quad * 16 + dl2;
            float inv = sinv[dl2];
            float a = src[(2 * hp) * 64 + d2] * inv;
            float c = src[(2 * hp + 1) * 64 + d2] * inv;
            dst[16384 + hp * 64 + (d2 ^ ((hp & 3) << 3))] = pack2(a, c);
        }
    }
}

// ======================= kernel 3: fp16 mma, software-pipelined chunks (frozen R13 winner) =======================
#define K3_XN_OFF 24640
#define K3_SMEM   ((24576 + 64 + 9216) * 4)   // 135424 B

__global__ __launch_bounds__(256, 1) void k3_main(const float* __restrict__ x,
                                                  const float* __restrict__ scale,
                                                  float* __restrict__ out) {
    extern __shared__ uint32_t su[];
    float* ssc = (float*)(su + 24576);       // scale [64]
    uint32_t* xnw = su + K3_XN_OFF;          // [256][36] half2 words
    const int tid = threadIdx.x, w = tid >> 5, lane = tid & 31;
    const int b = blockIdx.x >> 4;
    const int row0 = (blockIdx.x & 15) * 256;
    const int m0 = w * 32;
    const int r = lane >> 2, q = lane & 3, q8 = q << 3;
    const uint32_t sb = smem_u32(su);

    {
        const uint32_t* wsrc = g_wT + (size_t)b * WPB;
        #pragma unroll 6
        for (int i = tid; i < 6144; i += 256)
            cpa16(sb + (uint32_t)i * 16, wsrc + i * 4);
        CP_COMMIT();
    }
    if (tid < 64) ssc[tid] = scale[tid];
    __syncthreads();

    {
        const float4* xr = (const float4*)(x + ((size_t)b * NN + row0 + tid) * DD);
        float4 v[16];
        float ssq = 0.f;
        #pragma unroll
        for (int i = 0; i < 16; i++) {
            v[i] = xr[i];
            ssq += v[i].x * v[i].x + v[i].y * v[i].y + v[i].z * v[i].z + v[i].w * v[i].w;
        }
        const float rr = rsqrtf(ssq * (1.0f / 64.0f) + 1e-6f);
        uint32_t* xd = xnw + tid * 36;
        #pragma unroll
        for (int i = 0; i < 8; i++) {
            float4 a = v[2 * i], c = v[2 * i + 1];
            float4 sA = *(const float4*)&ssc[8 * i];
            float4 sB = *(const float4*)&ssc[8 * i + 4];
            uint4 o;
            o.x = pack2(a.x * rr * sA.x, a.y * rr * sA.y);
            o.y = pack2(a.z * rr * sA.z, a.w * rr * sA.w);
            o.z = pack2(c.x * rr * sB.x, c.y * rr * sB.y);
            o.w = pack2(c.z * rr * sB.z, c.w * rr * sB.w);
            *(uint4*)&xd[4 * i] = o;
        }
    }
    CP_WAIT0();
    __syncthreads();

    const uint32_t* Wg = su;
    const uint32_t* Wv = su + 8192;
    const uint32_t* Wf = su + 16384;

    uint32_t xa[4][2][4];
    #pragma unroll
    for (int kt = 0; kt < 4; kt++) {
        #pragma unroll
        for (int mf = 0; mf < 2; mf++) {
            const uint32_t* xb = xnw + (m0 + mf * 16 + r) * 36 + kt * 8 + q;
            xa[kt][mf][0] = xb[0];
            xa[kt][mf][1] = xb[8 * 36];
            xa[kt][mf][2] = xb[4];
            xa[kt][mf][3] = xb[8 * 36 + 4];
        }
    }

    float oacc[2][8][4];
    #pragma unroll
    for (int mf = 0; mf < 2; mf++)
        #pragma unroll
        for (int i = 0; i < 8; i++)
            oacc[mf][i][0] = oacc[mf][i][1] = oacc[mf][i][2] = oacc[mf][i][3] = 0.f;

    #define MMA1_CHUNK(ch, ga, va) do {                                             \
        const int _nc = (ch) * 16;                                                  \
        _Pragma("unroll")                                                           \
        for (int _mf = 0; _mf < 2; _mf++)                                           \
            _Pragma("unroll")                                                       \
            for (int _nt = 0; _nt < 2; _nt++) {                                     \
                (ga)[_mf][_nt][0] = (ga)[_mf][_nt][1] = (ga)[_mf][_nt][2] = (ga)[_mf][_nt][3] = 0.f; \
                (va)[_mf][_nt][0] = (va)[_mf][_nt][1] = (va)[_mf][_nt][2] = (va)[_mf][_nt][3] = 0.f; \
            }                                                                       \
        const int _c0 = (_nc ^ q8) + r;                                             \
        const int _c1 = ((_nc + 8) ^ q8) + r;                                       \
        _Pragma("unroll")                                                           \
        for (int _kt = 0; _kt < 4; _kt++) {                                         \
            const uint32_t* _g0 = Wg + (_kt * 8 + q) * 256;                         \
            const uint32_t* _g1 = Wg + (_kt * 8 + q + 4) * 256;                     \
            const uint32_t* _v0 = Wv + (_kt * 8 + q) * 256;                         \
            const uint32_t* _v1 = Wv + (_kt * 8 + q + 4) * 256;                     \
            uint32_t _gb00 = _g0[_c0], _gb10 = _g1[_c0], _gb01 = _g0[_c1], _gb11 = _g1[_c1]; \
            uint32_t _vb00 = _v0[_c0], _vb10 = _v1[_c0], _vb01 = _v0[_c1], _vb11 = _v1[_c1]; \
            _Pragma("unroll")                                                       \
            for (int _mf = 0; _mf < 2; _mf++) {                                     \
                mma_f16((ga)[_mf][0], xa[_kt][_mf], _gb00, _gb10);                  \
                mma_f16((ga)[_mf][1], xa[_kt][_mf], _gb01, _gb11);                  \
                mma_f16((va)[_mf][0], xa[_kt][_mf], _vb00, _vb10);                  \
                mma_f16((va)[_mf][1], xa[_kt][_mf], _vb01, _vb11);                  \
            }                                                                       \
        }                                                                           \
    } while (0)

    #define SILU_MMA2(ch, ga, va) do {                                              \
        const int _hp0 = (ch) * 8;                                                  \
        const uint32_t* _f0 = Wf + (_hp0 + q) * 64;                                 \
        const uint32_t* _f1 = Wf + (_hp0 + q + 4) * 64;                             \
        uint32_t _ha[2][4];                                                         \
        _Pragma("unroll")                                                           \
        for (int _mf = 0; _mf < 2; _mf++) {                                         \
            float _h00 = 0.5f * (ga)[_mf][0][0] * (1.f + tanha(0.5f * (ga)[_mf][0][0])) * (va)[_mf][0][0]; \
            float _h01 = 0.5f * (ga)[_mf][0][1] * (1.f + tanha(0.5f * (ga)[_mf][0][1])) * (va)[_mf][0][1]; \
            float _h02 = 0.5f * (ga)[_mf][0][2] * (1.f + tanha(0.5f * (ga)[_mf][0][2])) * (va)[_mf][0][2]; \
            float _h03 = 0.5f * (ga)[_mf][0][3] * (1.f + tanha(0.5f * (ga)[_mf][0][3])) * (va)[_mf][0][3]; \
            float _h10 = 0.5f * (ga)[_mf][1][0] * (1.f + tanha(0.5f * (ga)[_mf][1][0])) * (va)[_mf][1][0]; \
            float _h11 = 0.5f * (ga)[_mf][1][1] * (1.f + tanha(0.5f * (ga)[_mf][1][1])) * (va)[_mf][1][1]; \
            float _h12 = 0.5f * (ga)[_mf][1][2] * (1.f + tanha(0.5f * (ga)[_mf][1][2])) * (va)[_mf][1][2]; \
            float _h13 = 0.5f * (ga)[_mf][1][3] * (1.f + tanha(0.5f * (ga)[_mf][1][3])) * (va)[_mf][1][3]; \
            _ha[_mf][0] = pack2(_h00, _h01);                                        \
            _ha[_mf][1] = pack2(_h02, _h03);                                        \
            _ha[_mf][2] = pack2(_h10, _h11);                                        \
            _ha[_mf][3] = pack2(_h12, _h13);                                        \
        }                                                                           \
        _Pragma("unroll")                                                           \
        for (int _dt = 0; _dt < 8; _dt++) {                                         \
            const int _c = ((_dt * 8) ^ q8) + r;                                    \
            uint32_t _fb0 = _f0[_c], _fb1 = _f1[_c];                                \
            mma_f16(oacc[0][_dt], _ha[0], _fb0, _fb1);                              \
            mma_f16(oacc[1][_dt], _ha[1], _fb0, _fb1);                              \
        }                                                                           \
    } while (0)

    float gaA[2][2][4], vaA[2][2][4], gaB[2][2][4], vaB[2][2][4];
    MMA1_CHUNK(0, gaA, vaA);
    #pragma unroll 2
    for (int cp = 0; cp < 7; cp++) {
        const int ch = cp * 2;
        MMA1_CHUNK(ch + 1, gaB, vaB);
        SILU_MMA2(ch, gaA, vaA);
        MMA1_CHUNK(ch + 2, gaA, vaA);
        SILU_MMA2(ch + 1, gaB, vaB);
    }
    MMA1_CHUNK(15, gaB, vaB);
    SILU_MMA2(14, gaA, vaA);
    SILU_MMA2(15, gaB, vaB);

    #undef MMA1_CHUNK
    #undef SILU_MMA2

    #pragma unroll
    for (int mf = 0; mf < 2; mf++) {
        const int gr0 = row0 + m0 + mf * 16 + r;
        const float* x0 = x + ((size_t)b * NN + gr0) * DD;
        const float* x1 = x0 + 8 * DD;
        float* o0 = out + ((size_t)b * NN + gr0) * DD;
        float* o1 = o0 + 8 * DD;
        #pragma unroll
        for (int dt = 0; dt < 8; dt++) {
            const int cc = dt * 8 + 2 * q;
            float2 r0v = *(const float2*)(x0 + cc);
            float2 r1v = *(const float2*)(x1 + cc);
            *(float2*)(o0 + cc) = make_float2(oacc[mf][dt][0] + r0v.x, oacc[mf][dt][1] + r0v.y);
            *(float2*)(o1 + cc) = make_float2(oacc[mf][dt][2] + r1v.x, oacc[mf][dt][3] + r1v.y);
        }
    }
}

// ======================= launch =======================
extern "C" void kernel_launch(void* const* d_in, const int* in_sizes, int n_in,
                              void* d_out, int out_size) {
    const float* x     = (const float*)d_in[0];
    const float* s     = (const float*)d_in[1];
    const float* W     = (const float*)d_in[2];
    const float* bias  = (const float*)d_in[3];
    const float* scale = (const float*)d_in[4];
    float* out = (float*)d_out;

    cudaFuncSetAttribute(k1_mma, cudaFuncAttributeMaxDynamicSharedMemorySize, K1_SMEM);
    k1_mma<<<dim3(TOT / 128), 256, K1_SMEM>>>(s, W, bias);

    k2_normalize<<<dim3(64, 4), 256>>>();

    cudaFuncSetAttribute(k3_main, cudaFuncAttributeMaxDynamicSharedMemorySize, K3_SMEM);
    k3_main<<<dim3(1024), 256, K3_SMEM>>>(x, scale, out);
}

// round 15
// speedup vs baseline: 1.0902x; 1.0902x over previous
#include <cuda_runtime.h>
#include <cuda_fp16.h>
#include <cstdint>
#include <math.h>

#define BB   64
#define NN   4096
#define DD   64
#define HH   256
#define SS   1024
#define TOT  49152   // 3 * D * H
#define WPB  24576   // half2 words per batch (3*D*H/2)

// raw hypernet output (k1 -> k2)
__device__ float g_params[BB * (size_t)TOT];
// normalized fp16 weights, half2-packed along k, XOR-swizzled (k2 -> k3)
__device__ uint32_t g_wT[BB * (size_t)WPB];

// ======================= helpers =======================
__device__ __forceinline__ float tanha(float x) {
    float y;
    asm("tanh.approx.f32 %0, %1;" : "=f"(y) : "f"(x));
    return y;
}
__device__ __forceinline__ uint32_t pack2(float lo, float hi) {
    __half2 h = __floats2half2_rn(lo, hi);
    return *(uint32_t*)&h;
}
__device__ __forceinline__ uint32_t smem_u32(const void* p) {
    uint32_t a;
    asm("{ .reg .u64 t; cvta.to.shared.u64 t, %1; cvt.u32.u64 %0, t; }" : "=r"(a) : "l"(p));
    return a;
}
__device__ __forceinline__ void cpa16(uint32_t dst, const void* src) {
    asm volatile("cp.async.cg.shared.global [%0], [%1], 16;" :: "r"(dst), "l"(src));
}
#define CP_COMMIT() asm volatile("cp.async.commit_group;" ::: "memory")
#define CP_WAIT0()  asm volatile("cp.async.wait_group 0;" ::: "memory")
#define CP_WAIT1()  asm volatile("cp.async.wait_group 1;" ::: "memory")

// D += A * B  (m16n8k8, tf32 inputs, fp32 accum) — kernel 1
__device__ __forceinline__ void mma_tf32(float* d, const uint32_t* a, uint32_t b0, uint32_t b1) {
    asm volatile("mma.sync.aligned.m16n8k8.row.col.f32.tf32.tf32.f32 "
                 "{%0,%1,%2,%3}, {%4,%5,%6,%7}, {%8,%9}, {%0,%1,%2,%3};"
                 : "+f"(d[0]), "+f"(d[1]), "+f"(d[2]), "+f"(d[3])
                 : "r"(a[0]), "r"(a[1]), "r"(a[2]), "r"(a[3]), "r"(b0), "r"(b1));
}
// D += A * B  (m16n8k16, fp16 inputs, fp32 accum) — kernel 3
__device__ __forceinline__ void mma_f16(float* d, const uint32_t* a, uint32_t b0, uint32_t b1) {
    asm volatile("mma.sync.aligned.m16n8k16.row.col.f32.f16.f16.f32 "
                 "{%0,%1,%2,%3}, {%4,%5,%6,%7}, {%8,%9}, {%0,%1,%2,%3};"
                 : "+f"(d[0]), "+f"(d[1]), "+f"(d[2]), "+f"(d[3])
                 : "r"(a[0]), "r"(a[1]), "r"(a[2]), "r"(a[3]), "r"(b0), "r"(b1));
}

// ======================= kernel 1: hypernet GEMM via mma.sync tf32 (reverted R13, 58us) =======================
#define K1_SMEM ((2 * 64 * 36 + 2 * 32 * 136) * 4)   // 53248 B

__global__ __launch_bounds__(256) void k1_mma(const float* __restrict__ s,
                                              const float* __restrict__ W,
                                              const float* __restrict__ bias) {
    extern __shared__ float sk[];
    float* sA = sk;              // 2 * 2304
    float* sB = sk + 4608;       // 2 * 4352
    const int n0  = blockIdx.x * 128;
    const int tid = threadIdx.x;
    const int w = tid >> 5, lane = tid & 31;
    const int r = lane >> 2, q = lane & 3;
    const int m0 = (w & 1) * 32, nw = (w >> 1) * 32;
    const uint32_t sbA = smem_u32(sA), sbB = smem_u32(sB);

    #define K1_LOAD(st, k0) do {                                                   \
        _Pragma("unroll")                                                          \
        for (int i = 0; i < 2; i++) {                                              \
            int c = tid + i * 256;                                                 \
            int row = c >> 3, cc = c & 7;                                          \
            cpa16(sbA + (uint32_t)((st) * 2304 + row * 36 + cc * 4) * 4,           \
                  s + (size_t)row * SS + (k0) + cc * 4);                           \
        }                                                                          \
        _Pragma("unroll")                                                          \
        for (int i = 0; i < 4; i++) {                                              \
            int c = tid + i * 256;                                                 \
            int row = c >> 5, cc = c & 31;                                         \
            cpa16(sbB + (uint32_t)((st) * 4352 + row * 136 + cc * 4) * 4,          \
                  W + (size_t)((k0) + row) * TOT + n0 + cc * 4);                   \
        }                                                                          \
    } while (0)

    float acc[2][4][4];
    #pragma unroll
    for (int mf = 0; mf < 2; mf++)
        #pragma unroll
        for (int nf = 0; nf < 4; nf++)
            acc[mf][nf][0] = acc[mf][nf][1] = acc[mf][nf][2] = acc[mf][nf][3] = 0.f;

    K1_LOAD(0, 0);  CP_COMMIT();
    K1_LOAD(1, 32); CP_COMMIT();

    for (int ks = 0; ks < 32; ks++) {
        CP_WAIT1();
        __syncthreads();
        const int st = ks & 1;
        const float* A  = sA + st * 2304;
        const float* Bp = sB + st * 4352;
        #pragma unroll
        for (int kk = 0; kk < 4; kk++) {
            uint32_t a[2][4];
            #pragma unroll
            for (int mf = 0; mf < 2; mf++) {
                const int mr = m0 + mf * 16 + r;
                a[mf][0] = __float_as_uint(A[mr * 36 + kk * 8 + q]);
                a[mf][1] = __float_as_uint(A[(mr + 8) * 36 + kk * 8 + q]);
                a[mf][2] = __float_as_uint(A[mr * 36 + kk * 8 + q + 4]);
                a[mf][3] = __float_as_uint(A[(mr + 8) * 36 + kk * 8 + q + 4]);
            }
            #pragma unroll
            for (int nf = 0; nf < 4; nf++) {
                const int cb = nw + nf * 8 + r;
                uint32_t b0 = __float_as_uint(Bp[(kk * 8 + q) * 136 + cb]);
                uint32_t b1 = __float_as_uint(Bp[(kk * 8 + q + 4) * 136 + cb]);
                mma_tf32(acc[0][nf], a[0], b0, b1);
                mma_tf32(acc[1][nf], a[1], b0, b1);
            }
        }
        __syncthreads();
        const int kn = (ks + 2) * 32;
        if (kn < SS) { K1_LOAD(st, kn); }
        CP_COMMIT();
    }

    #pragma unroll
    for (int nf = 0; nf < 4; nf++) {
        float2 bv = *(const float2*)(bias + n0 + nw + nf * 8 + 2 * q);
        #pragma unroll
        for (int mf = 0; mf < 2; mf++) {
            const int mr = m0 + mf * 16 + r;
            float* o0 = g_params + (size_t)mr * TOT + n0 + nw + nf * 8 + 2 * q;
            *(float2*)o0 = make_float2(acc[mf][nf][0] + bv.x, acc[mf][nf][1] + bv.y);
            float* o1 = g_params + (size_t)(mr + 8) * TOT + n0 + nw + nf * 8 + 2 * q;
            *(float2*)o1 = make_float2(acc[mf][nf][2] + bv.x, acc[mf][nf][3] + bv.y);
        }
    }
    #undef K1_LOAD
}

// ======================= kernel 2: normalize -> fp16 swizzled, grid (64, 4) (frozen) =======================
__global__ __launch_bounds__(256) void k2_normalize() {
    __shared__ float red[256];
    __shared__ float sinv[64];
    const int b = blockIdx.x, quad = blockIdx.y, tid = threadIdx.x;
    const float* P = g_params + (size_t)b * TOT;
    uint32_t* dst = g_wT + (size_t)b * WPB;

    #pragma unroll
    for (int m = 0; m < 2; m++) {
        const float* src = P + m * 16384;
        const int hl = tid & 63, part = tid >> 6;
        const int h = quad * 64 + hl;
        {
            float ss = 0.f;
            #pragma unroll 4
            for (int d = part * 16; d < part * 16 + 16; d++) {
                float v = src[d * 256 + h];
                ss += v * v;
            }
            red[tid] = ss;
        }
        __syncthreads();
        if (tid < 64)
            sinv[tid] = 1.f / fmaxf(sqrtf(red[tid] + red[tid + 64] + red[tid + 128] + red[tid + 192]), 1e-12f);
        __syncthreads();
        #pragma unroll
        for (int i = 0; i < 8; i++) {
            int idx = tid + i * 256;
            int kp = idx >> 6, hl2 = idx & 63;
            int h2 = quad * 64 + hl2;
            float inv = sinv[hl2];
            float a = src[(2 * kp) * 256 + h2] * inv;
            float c = src[(2 * kp + 1) * 256 + h2] * inv;
            dst[m * 8192 + kp * 256 + (h2 ^ ((kp & 3) << 3))] = pack2(a, c);
        }
        __syncthreads();
    }
    {
        const float* src = P + 32768;
        const int dl = tid & 15, part = tid >> 4;
        const int d = quad * 16 + dl;
        {
            float ss = 0.f;
            #pragma unroll 4
            for (int h = part * 16; h < part * 16 + 16; h++) {
                float v = src[h * 64 + d];
                ss += v * v;
            }
            red[tid] = ss;
        }
        __syncthreads();
        if (tid < 16) {
            float t = 0.f;
            #pragma unroll
            for (int p = 0; p < 16; p++) t += red[p * 16 + tid];
            sinv[tid] = 1.f / fmaxf(sqrtf(t), 1e-12f);
        }
        __syncthreads();
        #pragma unroll
        for (int i = 0; i < 8; i++) {
            int idx = tid + i * 256;
            int hp = idx >> 4, dl2 = idx & 15;
            int d2 = quad * 16 + dl2;
            float inv = sinv[dl2];
            float a = src[(2 * hp) * 64 + d2] * inv;
            float c = src[(2 * hp + 1) * 64 + d2] * inv;
            dst[16384 + hp * 64 + (d2 ^ ((hp & 3) << 3))] = pack2(a, c);
        }
    }
}

// ======================= kernel 3: fp16 mma, pipelined + hoisted LDS =======================
#define K3_XN_OFF 24640
#define K3_SMEM   ((24576 + 64 + 9216) * 4)   // 135424 B

__global__ __launch_bounds__(256, 1) void k3_main(const float* __restrict__ x,
                                                  const float* __restrict__ scale,
                                                  float* __restrict__ out) {
    extern __shared__ uint32_t su[];
    float* ssc = (float*)(su + 24576);       // scale [64]
    uint32_t* xnw = su + K3_XN_OFF;          // [256][36] half2 words
    const int tid = threadIdx.x, w = tid >> 5, lane = tid & 31;
    const int b = blockIdx.x >> 4;
    const int row0 = (blockIdx.x & 15) * 256;
    const int m0 = w * 32;
    const int r = lane >> 2, q = lane & 3, q8 = q << 3;
    const uint32_t sb = smem_u32(su);

    {
        const uint32_t* wsrc = g_wT + (size_t)b * WPB;
        #pragma unroll 6
        for (int i = tid; i < 6144; i += 256)
            cpa16(sb + (uint32_t)i * 16, wsrc + i * 4);
        CP_COMMIT();
    }
    if (tid < 64) ssc[tid] = scale[tid];
    __syncthreads();

    // ---- stage RMSNorm'd xn: one thread per row ----
    {
        const float4* xr = (const float4*)(x + ((size_t)b * NN + row0 + tid) * DD);
        float4 v[16];
        float ssq = 0.f;
        #pragma unroll
        for (int i = 0; i < 16; i++) {
            v[i] = xr[i];
            ssq += v[i].x * v[i].x + v[i].y * v[i].y + v[i].z * v[i].z + v[i].w * v[i].w;
        }
        const float rr = rsqrtf(ssq * (1.0f / 64.0f) + 1e-6f);
        uint32_t* xd = xnw + tid * 36;
        #pragma unroll
        for (int i = 0; i < 8; i++) {
            float4 a = v[2 * i], c = v[2 * i + 1];
            float4 sA = *(const float4*)&ssc[8 * i];
            float4 sB = *(const float4*)&ssc[8 * i + 4];
            uint4 o;
            o.x = pack2(a.x * rr * sA.x, a.y * rr * sA.y);
            o.y = pack2(a.z * rr * sA.z, a.w * rr * sA.w);
            o.z = pack2(c.x * rr * sB.x, c.y * rr * sB.y);
            o.w = pack2(c.z * rr * sB.z, c.w * rr * sB.w);
            *(uint4*)&xd[4 * i] = o;
        }
    }
    CP_WAIT0();
    __syncthreads();

    const uint32_t* Wg = su;
    const uint32_t* Wv = su + 8192;
    const uint32_t* Wf = su + 16384;

    // ---- cache A fragments: 4 k16 tiles x 2 m-frags (32 regs) ----
    uint32_t xa[4][2][4];
    #pragma unroll
    for (int kt = 0; kt < 4; kt++) {
        #pragma unroll
        for (int mf = 0; mf < 2; mf++) {
            const uint32_t* xb = xnw + (m0 + mf * 16 + r) * 36 + kt * 8 + q;
            xa[kt][mf][0] = xb[0];
            xa[kt][mf][1] = xb[8 * 36];
            xa[kt][mf][2] = xb[4];
            xa[kt][mf][3] = xb[8 * 36 + 4];
        }
    }

    float oacc[2][8][4];
    #pragma unroll
    for (int mf = 0; mf < 2; mf++)
        #pragma unroll
        for (int i = 0; i < 8; i++)
            oacc[mf][i][0] = oacc[mf][i][1] = oacc[mf][i][2] = oacc[mf][i][3] = 0.f;

    // ---- MMA1 for one 16-col chunk: prefetch next-kt B words before issuing current kt mmas ----
    #define MMA1_CHUNK(ch, ga, va) do {                                             \
        const int _nc = (ch) * 16;                                                  \
        _Pragma("unroll")                                                           \
        for (int _mf = 0; _mf < 2; _mf++)                                           \
            _Pragma("unroll")                                                       \
            for (int _nt = 0; _nt < 2; _nt++) {                                     \
                (ga)[_mf][_nt][0] = (ga)[_mf][_nt][1] = (ga)[_mf][_nt][2] = (ga)[_mf][_nt][3] = 0.f; \
                (va)[_mf][_nt][0] = (va)[_mf][_nt][1] = (va)[_mf][_nt][2] = (va)[_mf][_nt][3] = 0.f; \
            }                                                                       \
        const int _c0 = (_nc ^ q8) + r;                                             \
        const int _c1 = ((_nc + 8) ^ q8) + r;                                       \
        uint32_t _cg00, _cg10, _cg01, _cg11, _cv00, _cv10, _cv01, _cv11;            \
        {                                                                           \
            const uint32_t* _g0 = Wg + q * 256;                                     \
            const uint32_t* _g1 = Wg + (q + 4) * 256;                               \
            const uint32_t* _v0 = Wv + q * 256;                                     \
            const uint32_t* _v1 = Wv + (q + 4) * 256;                               \
            _cg00 = _g0[_c0]; _cg10 = _g1[_c0]; _cg01 = _g0[_c1]; _cg11 = _g1[_c1]; \
            _cv00 = _v0[_c0]; _cv10 = _v1[_c0]; _cv01 = _v0[_c1]; _cv11 = _v1[_c1]; \
        }                                                                           \
        _Pragma("unroll")                                                           \
        for (int _kt = 0; _kt < 4; _kt++) {                                         \
            uint32_t _gb00 = _cg00, _gb10 = _cg10, _gb01 = _cg01, _gb11 = _cg11;    \
            uint32_t _vb00 = _cv00, _vb10 = _cv10, _vb01 = _cv01, _vb11 = _cv11;    \
            if (_kt < 3) {                                                          \
                const uint32_t* _g0 = Wg + ((_kt + 1) * 8 + q) * 256;               \
                const uint32_t* _g1 = Wg + ((_kt + 1) * 8 + q + 4) * 256;           \
                const uint32_t* _v0 = Wv + ((_kt + 1) * 8 + q) * 256;               \
                const uint32_t* _v1 = Wv + ((_kt + 1) * 8 + q + 4) * 256;           \
                _cg00 = _g0[_c0]; _cg10 = _g1[_c0]; _cg01 = _g0[_c1]; _cg11 = _g1[_c1]; \
                _cv00 = _v0[_c0]; _cv10 = _v1[_c0]; _cv01 = _v0[_c1]; _cv11 = _v1[_c1]; \
            }                                                                       \
            _Pragma("unroll")                                                       \
            for (int _mf = 0; _mf < 2; _mf++) {                                     \
                mma_f16((ga)[_mf][0], xa[_kt][_mf], _gb00, _gb10);                  \
                mma_f16((ga)[_mf][1], xa[_kt][_mf], _gb01, _gb11);                  \
                mma_f16((va)[_mf][0], xa[_kt][_mf], _vb00, _vb10);                  \
                mma_f16((va)[_mf][1], xa[_kt][_mf], _vb01, _vb11);                  \
            }                                                                       \
        }                                                                           \
    } while (0)

    // ---- silu + MMA2: Wf fragment LDS hoisted above the MUFU block ----
    #define SILU_MMA2(ch, ga, va) do {                                              \
        const int _hp0 = (ch) * 8;                                                  \
        const uint32_t* _f0 = Wf + (_hp0 + q) * 64;                                 \
        const uint32_t* _f1 = Wf + (_hp0 + q + 4) * 64;                             \
        uint32_t _fb0[8], _fb1[8];                                                  \
        _Pragma("unroll")                                                           \
        for (int _dt = 0; _dt < 8; _dt++) {                                         \
            const int _c = ((_dt * 8) ^ q8) + r;                                    \
            _fb0[_dt] = _f0[_c]; _fb1[_dt] = _f1[_c];                               \
        }                                                                           \
        uint32_t _ha[2][4];                                                         \
        _Pragma("unroll")                                                           \
        for (int _mf = 0; _mf < 2; _mf++) {                                         \
            float _h00 = 0.5f * (ga)[_mf][0][0] * (1.f + tanha(0.5f * (ga)[_mf][0][0])) * (va)[_mf][0][0]; \
            float _h01 = 0.5f * (ga)[_mf][0][1] * (1.f + tanha(0.5f * (ga)[_mf][0][1])) * (va)[_mf][0][1]; \
            float _h02 = 0.5f * (ga)[_mf][0][2] * (1.f + tanha(0.5f * (ga)[_mf][0][2])) * (va)[_mf][0][2]; \
            float _h03 = 0.5f * (ga)[_mf][0][3] * (1.f + tanha(0.5f * (ga)[_mf][0][3])) * (va)[_mf][0][3]; \
            float _h10 = 0.5f * (ga)[_mf][1][0] * (1.f + tanha(0.5f * (ga)[_mf][1][0])) * (va)[_mf][1][0]; \
            float _h11 = 0.5f * (ga)[_mf][1][1] * (1.f + tanha(0.5f * (ga)[_mf][1][1])) * (va)[_mf][1][1]; \
            float _h12 = 0.5f * (ga)[_mf][1][2] * (1.f + tanha(0.5f * (ga)[_mf][1][2])) * (va)[_mf][1][2]; \
            float _h13 = 0.5f * (ga)[_mf][1][3] * (1.f + tanha(0.5f * (ga)[_mf][1][3])) * (va)[_mf][1][3]; \
            _ha[_mf][0] = pack2(_h00, _h01);                                        \
            _ha[_mf][1] = pack2(_h02, _h03);                                        \
            _ha[_mf][2] = pack2(_h10, _h11);                                        \
            _ha[_mf][3] = pack2(_h12, _h13);                                        \
        }                                                                           \
        _Pragma("unroll")                                                           \
        for (int _dt = 0; _dt < 8; _dt++) {                                         \
            mma_f16(oacc[0][_dt], _ha[0], _fb0[_dt], _fb1[_dt]);                    \
            mma_f16(oacc[1][_dt], _ha[1], _fb0[_dt], _fb1[_dt]);                    \
        }                                                                           \
    } while (0)

    // ---- software-pipelined chunk loop ----
    float gaA[2][2][4], vaA[2][2][4], gaB[2][2][4], vaB[2][2][4];
    MMA1_CHUNK(0, gaA, vaA);
    #pragma unroll 2
    for (int cp = 0; cp < 7; cp++) {
        const int ch = cp * 2;
        MMA1_CHUNK(ch + 1, gaB, vaB);
        SILU_MMA2(ch, gaA, vaA);
        MMA1_CHUNK(ch + 2, gaA, vaA);
        SILU_MMA2(ch + 1, gaB, vaB);
    }
    MMA1_CHUNK(15, gaB, vaB);
    SILU_MMA2(14, gaA, vaA);
    SILU_MMA2(15, gaB, vaB);

    #undef MMA1_CHUNK
    #undef SILU_MMA2

    // ---- epilogue: residual + store; warp owns out[32 x 64] ----
    #pragma unroll
    for (int mf = 0; mf < 2; mf++) {
        const int gr0 = row0 + m0 + mf * 16 + r;
        const float* x0 = x + ((size_t)b * NN + gr0) * DD;
        const float* x1 = x0 + 8 * DD;
        float* o0 = out + ((size_t)b * NN + gr0) * DD;
        float* o1 = o0 + 8 * DD;
        #pragma unroll
        for (int dt = 0; dt < 8; dt++) {
            const int cc = dt * 8 + 2 * q;
            float2 r0v = *(const float2*)(x0 + cc);
            float2 r1v = *(const float2*)(x1 + cc);
            *(float2*)(o0 + cc) = make_float2(oacc[mf][dt][0] + r0v.x, oacc[mf][dt][1] + r0v.y);
            *(float2*)(o1 + cc) = make_float2(oacc[mf][dt][2] + r1v.x, oacc[mf][dt][3] + r1v.y);
        }
    }
}

// ======================= launch =======================
extern "C" void kernel_launch(void* const* d_in, const int* in_sizes, int n_in,
                              void* d_out, int out_size) {
    const float* x     = (const float*)d_in[0];
    const float* s     = (const float*)d_in[1];
    const float* W     = (const float*)d_in[2];
    const float* bias  = (const float*)d_in[3];
    const float* scale = (const float*)d_in[4];
    float* out = (float*)d_out;

    cudaFuncSetAttribute(k1_mma, cudaFuncAttributeMaxDynamicSharedMemorySize, K1_SMEM);
    k1_mma<<<dim3(TOT / 128), 256, K1_SMEM>>>(s, W, bias);

    k2_normalize<<<dim3(64, 4), 256>>>();

    cudaFuncSetAttribute(k3_main, cudaFuncAttributeMaxDynamicSharedMemorySize, K3_SMEM);
    k3_main<<<dim3(1024), 256, K3_SMEM>>>(x, scale, out);
}